// round 6
// baseline (speedup 1.0000x reference)
#include <cuda_runtime.h>
#include <cuda_bf16.h>
#include <cstdint>

// PQLinear: out[8192,4096] = X[8192,4096] @ W^T (W gathered from PQ codebooks).
// R6: tf32 mma.sync GEMM. Changes vs R5:
//  - CTA tile 128x256 (8 warps, warp 64x64), 1 CTA/SM, half the barriers/MMA
//  - STAGES=3 cp.async ring, loop order wait->sync->load->compute (fixes the
//    stage-overwrite race R5 had with lookahead==stages-1 and pre-sync loads)
//  - mainloop still pure LDS.64 + HMMA (tf32 rounding + k-pair permute in prep)

#define M_TOT 8192
#define N_TOT 4096
#define K_TOT 4096
#define BM 128
#define BN 256
#define BK 32
#define SBK 40
#define STAGES 3
#define NCHUNK (K_TOT / BK)            // 128
#define A_STAGE_FLOATS (BM * SBK)      // 5120
#define B_STAGE_FLOATS (BN * SBK)      // 10240
#define SM_B_OFF (STAGES * A_STAGE_FLOATS)
#define SMEM_BYTES ((STAGES * (A_STAGE_FLOATS + B_STAGE_FLOATS)) * 4)   // 184320

__device__ float g_Xr[(size_t)M_TOT * K_TOT];   // rounded + k-permuted X
__device__ float g_Wr[(size_t)N_TOT * K_TOT];   // gathered + rounded + k-permuted W

// ---------------- helpers ----------------
__device__ __forceinline__ uint32_t smem_u32(const void* p) {
    uint32_t a;
    asm("{ .reg .u64 t; cvta.to.shared.u64 t, %1; cvt.u32.u64 %0, t; }" : "=r"(a) : "l"(p));
    return a;
}
__device__ __forceinline__ float rna_tf32f(float f) {
    uint32_t o; asm("cvt.rna.tf32.f32 %0, %1;" : "=r"(o) : "f"(f));
    return __uint_as_float(o);
}
__device__ __forceinline__ void cpa16(uint32_t saddr, const void* gaddr) {
    asm volatile("cp.async.cg.shared.global [%0], [%1], 16;" :: "r"(saddr), "l"(gaddr));
}
__device__ __forceinline__ void cp_commit() { asm volatile("cp.async.commit_group;" ::: "memory"); }
template <int N>
__device__ __forceinline__ void cp_wait() { asm volatile("cp.async.wait_group %0;" :: "n"(N) : "memory"); }

__device__ __forceinline__ void mma_tf32(float* c, const uint32_t* a, const uint32_t* b) {
    asm volatile(
        "mma.sync.aligned.m16n8k8.row.col.f32.tf32.tf32.f32 "
        "{%0,%1,%2,%3}, {%4,%5,%6,%7}, {%8,%9}, {%0,%1,%2,%3};"
        : "+f"(c[0]), "+f"(c[1]), "+f"(c[2]), "+f"(c[3])
        : "r"(a[0]), "r"(a[1]), "r"(a[2]), "r"(a[3]), "r"(b[0]), "r"(b[1]));
}

// ---------------- prep: round X to tf32 + permute k pairs ----------------
// within each 8-k group, new layout = {k0,k4,k1,k5,k2,k6,k3,k7}
__global__ void prep_x_kernel(const float* __restrict__ x) {
    const size_t ngrp = (size_t)M_TOT * K_TOT / 8;
    for (size_t g = blockIdx.x * blockDim.x + threadIdx.x; g < ngrp;
         g += (size_t)gridDim.x * blockDim.x) {
        const float4* s = (const float4*)(x + g * 8);
        float4 a = s[0], b = s[1];
        float4* d = (float4*)(g_Xr + g * 8);
        d[0] = make_float4(rna_tf32f(a.x), rna_tf32f(b.x), rna_tf32f(a.y), rna_tf32f(b.y));
        d[1] = make_float4(rna_tf32f(a.z), rna_tf32f(b.z), rna_tf32f(a.w), rna_tf32f(b.w));
    }
}

// gather W rows, round to tf32, permute k pairs
__global__ void build_w_kernel(const float* __restrict__ cb, const int* __restrict__ assign) {
    const int o = blockIdx.x;     // 0..4095
    const int j = threadIdx.x;    // 0..127
    const int p  = j & 7;
    const int np = (p < 4) ? (2 * p) : (2 * p - 7);
    const int jd = (j & ~7) + np;
    float* wrow = &g_Wr[(size_t)o * K_TOT];
#pragma unroll 1
    for (int s = 0; s < 32; s++) {
        const int code = __ldg(&assign[o * 32 + s]);
        wrow[s * 128 + jd] = rna_tf32f(cb[((size_t)(s * 256 + code)) * 128 + j]);
    }
}

// ---------------- GEMM ----------------
__global__ __launch_bounds__(256, 1) void pq_tf32_gemm(float* __restrict__ out)
{
    const float* __restrict__ A = g_Xr;
    const float* __restrict__ B = g_Wr;

    extern __shared__ float smem[];
    float* As = smem;               // [STAGES][BM][SBK]
    float* Bs = smem + SM_B_OFF;    // [STAGES][BN][SBK]
    const uint32_t sbase = smem_u32(smem);

    const int tid  = threadIdx.x;
    const int wid  = tid >> 5;      // 0..7
    const int lane = tid & 31;
    const int lq   = lane >> 2;     // 0..7
    const int lr   = lane & 3;      // 0..3

    // grid: 64 m-tiles x 16 n-tiles; swizzle in 8x8 groups
    const int bid = blockIdx.x;
    const int grp = bid >> 6;                   // 0..15
    const int r   = bid & 63;
    const int mt  = (grp & 7) * 8 + (r & 7);    // 0..63
    const int nt  = (grp >> 3) * 8 + (r >> 3);  // 0..15
    const int m0  = mt * BM;
    const int n0  = nt * BN;

    // warp grid 2x4: warp tile 64x64
    const int wm = (wid >> 2) * 64;             // 0 or 64
    const int wn = (wid & 3) * 64;              // 0..192

    float acc[4][8][4];
#pragma unroll
    for (int mi = 0; mi < 4; mi++)
#pragma unroll
        for (int ni = 0; ni < 8; ni++)
#pragma unroll
            for (int q = 0; q < 4; q++) acc[mi][ni][q] = 0.f;

    // stage loads: A = 128 rows x 8 f4 (4/thread), B = 256 rows x 8 f4 (8/thread)
    const int l_row = tid >> 3;     // 0..31
    const int l_c   = tid & 7;

    auto load_stage = [&](int chunk) {
        const int st = chunk % STAGES;
        const int k0 = chunk * BK;
        const uint32_t abase = sbase + (st * A_STAGE_FLOATS) * 4;
        const uint32_t bbase = sbase + ((SM_B_OFF + st * B_STAGE_FLOATS)) * 4;
#pragma unroll
        for (int p = 0; p < 4; p++) {
            const int row = l_row + p * 32;
            cpa16(abase + (row * SBK + l_c * 4) * 4,
                  A + (size_t)(m0 + row) * K_TOT + k0 + l_c * 4);
        }
#pragma unroll
        for (int p = 0; p < 8; p++) {
            const int row = l_row + p * 32;
            cpa16(bbase + (row * SBK + l_c * 4) * 4,
                  B + (size_t)(n0 + row) * K_TOT + k0 + l_c * 4);
        }
    };

    // prologue: chunks 0..STAGES-2 (lookahead = 2)
#pragma unroll
    for (int c = 0; c < STAGES - 1; c++) { load_stage(c); cp_commit(); }

#pragma unroll 1
    for (int i = 0; i < NCHUNK; i++) {
        cp_wait<STAGES - 2>();          // chunk i has landed
        __syncthreads();                // all warps done with stage being overwritten
        if (i + STAGES - 1 < NCHUNK) load_stage(i + STAGES - 1);
        cp_commit();

        const float* as = As + (i % STAGES) * A_STAGE_FLOATS;
        const float* bs = Bs + (i % STAGES) * B_STAGE_FLOATS;

#pragma unroll
        for (int kg = 0; kg < 4; kg++) {
            const int kb = kg * 8 + 2 * lr;     // permuted-pair offset
            uint32_t af[4][4], bf[8][2];
#pragma unroll
            for (int mi = 0; mi < 4; mi++) {
                const int rw = wm + mi * 16 + lq;
                const float2 v0 = *(const float2*)(as + rw * SBK + kb);
                const float2 v1 = *(const float2*)(as + (rw + 8) * SBK + kb);
                af[mi][0] = __float_as_uint(v0.x);
                af[mi][1] = __float_as_uint(v1.x);
                af[mi][2] = __float_as_uint(v0.y);
                af[mi][3] = __float_as_uint(v1.y);
            }
#pragma unroll
            for (int ni = 0; ni < 8; ni++) {
                const int cw = wn + ni * 8 + lq;
                const float2 v = *(const float2*)(bs + cw * SBK + kb);
                bf[ni][0] = __float_as_uint(v.x);
                bf[ni][1] = __float_as_uint(v.y);
            }
#pragma unroll
            for (int mi = 0; mi < 4; mi++)
#pragma unroll
                for (int ni = 0; ni < 8; ni++)
                    mma_tf32(acc[mi][ni], af[mi], bf[ni]);
        }
        __syncthreads();                // compute done before next overwrite window
    }

    // epilogue: float2 stores
#pragma unroll
    for (int mi = 0; mi < 4; mi++) {
#pragma unroll
        for (int ni = 0; ni < 8; ni++) {
            const int row0 = m0 + wm + mi * 16 + lq;
            const int col  = n0 + wn + ni * 8 + 2 * lr;
            *(float2*)&out[(size_t)row0 * N_TOT + col] =
                make_float2(acc[mi][ni][0], acc[mi][ni][1]);
            *(float2*)&out[(size_t)(row0 + 8) * N_TOT + col] =
                make_float2(acc[mi][ni][2], acc[mi][ni][3]);
        }
    }
}

extern "C" void kernel_launch(void* const* d_in, const int* in_sizes, int n_in,
                              void* d_out, int out_size) {
    const float* x         = (const float*)d_in[0];   // [4,2048,4096] fp32
    const float* codebooks = (const float*)d_in[1];   // [32,256,128] fp32
    const int*   assign    = (const int*)d_in[2];     // [4096,32] int32
    float*       out       = (float*)d_out;

    prep_x_kernel<<<8192, 256>>>(x);
    build_w_kernel<<<4096, 128>>>(codebooks, assign);

    cudaFuncSetAttribute(pq_tf32_gemm,
                         cudaFuncAttributeMaxDynamicSharedMemorySize, SMEM_BYTES);
    pq_tf32_gemm<<<(M_TOT / BM) * (N_TOT / BN), 256, SMEM_BYTES>>>(out);
}

// round 7
// speedup vs baseline: 1.8552x; 1.8552x over previous
#include <cuda_runtime.h>
#include <cuda_fp16.h>
#include <cstdint>

// PQLinear: out[8192,4096] = X[8192,4096] @ W^T (W gathered from PQ codebooks).
// R7: fp16 mma.sync.m16n8k16 GEMM (fp32 accum). fp16 mantissa == tf32 mantissa
// -> same ~3e-4 error, but 2x FLOP/instruction and half the smem traffic.
//  - R5 structure (CTA 128x128, 4 warps of 64x64, 2 CTAs/SM), STAGES=3
//  - k-permuted fp16 layout: every fragment pair is one LDS.64
//  - row stride 48 halves (96B): conflict-free 64-bit LDS

#define M_TOT 8192
#define N_TOT 4096
#define K_TOT 4096
#define BM 128
#define BN 128
#define BK 32                        // halves per chunk
#define PADH 48                      // smem row stride in halves (96 B)
#define STAGES 3
#define NCHUNK (K_TOT / BK)          // 128
#define STAGE_HALVES (BM * PADH)     // 6144 (12288 B per operand-stage)
#define SM_B_OFF (STAGES * STAGE_HALVES)
#define SMEM_BYTES (2 * STAGES * STAGE_HALVES * 2)   // 73728

__device__ __half g_Xh[(size_t)M_TOT * K_TOT];   // 64 MB fp16 permuted X
__device__ __half g_Wh[(size_t)N_TOT * K_TOT];   // 32 MB fp16 gathered+permuted W

// ---------------- helpers ----------------
__device__ __forceinline__ uint32_t smem_u32(const void* p) {
    uint32_t a;
    asm("{ .reg .u64 t; cvta.to.shared.u64 t, %1; cvt.u32.u64 %0, t; }" : "=r"(a) : "l"(p));
    return a;
}
__device__ __forceinline__ void cpa16(uint32_t saddr, const void* gaddr) {
    asm volatile("cp.async.cg.shared.global [%0], [%1], 16;" :: "r"(saddr), "l"(gaddr));
}
__device__ __forceinline__ void cp_commit() { asm volatile("cp.async.commit_group;" ::: "memory"); }
template <int N>
__device__ __forceinline__ void cp_wait() { asm volatile("cp.async.wait_group %0;" :: "n"(N) : "memory"); }

__device__ __forceinline__ void mma_f16(float* c, const uint32_t* a, const uint32_t* b) {
    asm volatile(
        "mma.sync.aligned.m16n8k16.row.col.f32.f16.f16.f32 "
        "{%0,%1,%2,%3}, {%4,%5,%6,%7}, {%8,%9}, {%0,%1,%2,%3};"
        : "+f"(c[0]), "+f"(c[1]), "+f"(c[2]), "+f"(c[3])
        : "r"(a[0]), "r"(a[1]), "r"(a[2]), "r"(a[3]), "r"(b[0]), "r"(b[1]));
}

// ---------------- prep ----------------
// Within each 16-k group, store half2 pairs in order:
// {k0k1, k8k9, k2k3, k10k11, k4k5, k12k13, k6k7, k14k15}
// -> source pair index for output pair j: s(j) = (j&1)*4 + (j>>1)
__global__ void prep_x_kernel(const float* __restrict__ x) {
    const size_t ngrp = (size_t)M_TOT * K_TOT / 16;
    for (size_t g = blockIdx.x * blockDim.x + threadIdx.x; g < ngrp;
         g += (size_t)gridDim.x * blockDim.x) {
        const float2* s = (const float2*)(x + g * 16);   // 8 source pairs
        float2 sp[8];
#pragma unroll
        for (int j = 0; j < 8; j++) sp[j] = s[j];
        __half2 op[8];
#pragma unroll
        for (int j = 0; j < 8; j++) {
            const float2 v = sp[(j & 1) * 4 + (j >> 1)];
            op[j] = __floats2half2_rn(v.x, v.y);
        }
        *(uint4*)(g_Xh + g * 16)     = *(const uint4*)&op[0];
        *(uint4*)(g_Xh + g * 16 + 8) = *(const uint4*)&op[4];
    }
}

__global__ void build_w_kernel(const float* __restrict__ cb, const int* __restrict__ assign) {
    const int o = blockIdx.x;     // 0..4095
    const int j = threadIdx.x;    // 0..127
    const int t = j & 15;
    const int jd = (j & ~15) + (((t & 7) >> 1) << 2) + ((t >> 3) << 1) + (t & 1);
    __half* wrow = &g_Wh[(size_t)o * K_TOT];
#pragma unroll 1
    for (int s = 0; s < 32; s++) {
        const int code = __ldg(&assign[o * 32 + s]);
        wrow[s * 128 + jd] = __float2half_rn(cb[((size_t)(s * 256 + code)) * 128 + j]);
    }
}

// ---------------- GEMM ----------------
__global__ __launch_bounds__(128, 2) void pq_f16_gemm(float* __restrict__ out)
{
    const __half* __restrict__ A = g_Xh;
    const __half* __restrict__ B = g_Wh;

    extern __shared__ __half smem[];
    __half* As = smem;               // [STAGES][BM][PADH]
    __half* Bs = smem + SM_B_OFF;    // [STAGES][BN][PADH]
    const uint32_t sbase = smem_u32(smem);

    const int tid  = threadIdx.x;
    const int wid  = tid >> 5;       // 0..3
    const int lane = tid & 31;
    const int lq   = lane >> 2;      // 0..7
    const int lr   = lane & 3;       // 0..3

    // grid swizzle: 8x8 tile groups
    const int bid = blockIdx.x;
    const int grp = bid >> 6;
    const int r   = bid & 63;
    const int mt  = (grp & 7) * 8 + (r & 7);
    const int nt  = (grp >> 3) * 8 + (r >> 3);
    const int m0  = mt * BM;
    const int n0  = nt * BN;

    // warp tile 64x64 (2x2 warps)
    const int wm = (wid >> 1) * 64;
    const int wn = (wid & 1) * 64;

    float acc[4][8][4];
#pragma unroll
    for (int mi = 0; mi < 4; mi++)
#pragma unroll
        for (int ni = 0; ni < 8; ni++)
#pragma unroll
            for (int q = 0; q < 4; q++) acc[mi][ni][q] = 0.f;

    // stage load: per operand 128 rows x 4 x 16B; 128 threads -> 4 each
    const int l_row = tid >> 2;      // 0..31 (x4 passes)
    const int l_c   = tid & 3;       // 16B chunk

    auto load_stage = [&](int chunk) {
        const int st = chunk % STAGES;
        const int k0 = chunk * BK;
        const uint32_t abase = sbase + (st * STAGE_HALVES) * 2;
        const uint32_t bbase = sbase + ((SM_B_OFF + st * STAGE_HALVES)) * 2;
#pragma unroll
        for (int p = 0; p < 4; p++) {
            const int row = l_row + p * 32;
            cpa16(abase + row * (PADH * 2) + l_c * 16,
                  A + (size_t)(m0 + row) * K_TOT + k0 + l_c * 8);
            cpa16(bbase + row * (PADH * 2) + l_c * 16,
                  B + (size_t)(n0 + row) * K_TOT + k0 + l_c * 8);
        }
    };

#pragma unroll
    for (int c = 0; c < STAGES - 1; c++) { load_stage(c); cp_commit(); }

#pragma unroll 1
    for (int i = 0; i < NCHUNK; i++) {
        if (i + STAGES - 1 < NCHUNK) load_stage(i + STAGES - 1);
        cp_commit();
        cp_wait<STAGES - 1>();       // chunk i resident (S-1 groups may be in flight)
        __syncthreads();

        const __half* as = As + (i % STAGES) * STAGE_HALVES;
        const __half* bs = Bs + (i % STAGES) * STAGE_HALVES;

#pragma unroll
        for (int kg = 0; kg < 2; kg++) {             // two k16 steps
            const int koff = kg * 16 + lr * 4;       // halves
            uint32_t af[4][4], bf[8][2];
#pragma unroll
            for (int mi = 0; mi < 4; mi++) {
                const int rw = wm + mi * 16 + lq;
                const uint2 v0 = *(const uint2*)(as + rw * PADH + koff);
                const uint2 v1 = *(const uint2*)(as + (rw + 8) * PADH + koff);
                af[mi][0] = v0.x;    // {k2lr, k2lr+1}
                af[mi][1] = v1.x;
                af[mi][2] = v0.y;    // {k2lr+8, k2lr+9}
                af[mi][3] = v1.y;
            }
#pragma unroll
            for (int ni = 0; ni < 8; ni++) {
                const int cw = wn + ni * 8 + lq;
                const uint2 v = *(const uint2*)(bs + cw * PADH + koff);
                bf[ni][0] = v.x;
                bf[ni][1] = v.y;
            }
#pragma unroll
            for (int mi = 0; mi < 4; mi++)
#pragma unroll
                for (int ni = 0; ni < 8; ni++)
                    mma_f16(acc[mi][ni], af[mi], bf[ni]);
        }
        __syncthreads();
    }

    // epilogue
#pragma unroll
    for (int mi = 0; mi < 4; mi++) {
#pragma unroll
        for (int ni = 0; ni < 8; ni++) {
            const int row0 = m0 + wm + mi * 16 + lq;
            const int col  = n0 + wn + ni * 8 + 2 * lr;
            *(float2*)&out[(size_t)row0 * N_TOT + col] =
                make_float2(acc[mi][ni][0], acc[mi][ni][1]);
            *(float2*)&out[(size_t)(row0 + 8) * N_TOT + col] =
                make_float2(acc[mi][ni][2], acc[mi][ni][3]);
        }
    }
}

extern "C" void kernel_launch(void* const* d_in, const int* in_sizes, int n_in,
                              void* d_out, int out_size) {
    const float* x         = (const float*)d_in[0];   // [4,2048,4096] fp32
    const float* codebooks = (const float*)d_in[1];   // [32,256,128] fp32
    const int*   assign    = (const int*)d_in[2];     // [4096,32] int32
    float*       out       = (float*)d_out;

    prep_x_kernel<<<4096, 256>>>(x);
    build_w_kernel<<<4096, 128>>>(codebooks, assign);

    cudaFuncSetAttribute(pq_f16_gemm,
                         cudaFuncAttributeMaxDynamicSharedMemorySize, SMEM_BYTES);
    pq_f16_gemm<<<(M_TOT / BM) * (N_TOT / BN), 128, SMEM_BYTES>>>(out);
}

// round 9
// speedup vs baseline: 2.3065x; 1.2433x over previous
#include <cuda_runtime.h>
#include <cuda_fp16.h>
#include <cstdint>

// PQLinear: out[8192,4096] = X[8192,4096] @ W^T (W gathered from PQ codebooks).
// R9: fp16 m16n8k16 GEMM. Same plan as R8 with the ldmatrix SW128 address bug
// fixed: swizzled addr = row*128 + ((col+ko) ^ ((row&7)*16)) — column XORed
// inside the row, never added past it (R8 overflowed smem on the last stage).

#define M_TOT 8192
#define N_TOT 4096
#define K_TOT 4096
#define BM 128
#define BN 128
#define BK 64                         // halves per chunk (128 B rows)
#define STAGES 3
#define NCHUNK (K_TOT / BK)           // 64
#define A_STAGE_BYTES (BM * 128)      // 16384
#define B_STAGE_BYTES (BN * 128)      // 16384
#define SM_B_OFF (STAGES * A_STAGE_BYTES)
#define SMEM_BYTES (STAGES * (A_STAGE_BYTES + B_STAGE_BYTES))   // 98304

__device__ __half g_Xh[(size_t)M_TOT * K_TOT];   // 64 MB fp16 X
__device__ __half g_Wh[(size_t)N_TOT * K_TOT];   // 32 MB fp16 gathered W

// ---------------- helpers ----------------
__device__ __forceinline__ uint32_t smem_u32(const void* p) {
    uint32_t a;
    asm("{ .reg .u64 t; cvta.to.shared.u64 t, %1; cvt.u32.u64 %0, t; }" : "=r"(a) : "l"(p));
    return a;
}
__device__ __forceinline__ void cpa16(uint32_t saddr, const void* gaddr) {
    asm volatile("cp.async.cg.shared.global [%0], [%1], 16;" :: "r"(saddr), "l"(gaddr));
}
__device__ __forceinline__ void cp_commit() { asm volatile("cp.async.commit_group;" ::: "memory"); }
template <int N>
__device__ __forceinline__ void cp_wait() { asm volatile("cp.async.wait_group %0;" :: "n"(N) : "memory"); }

__device__ __forceinline__ void ldsm4(uint32_t* r, uint32_t addr) {
    asm volatile("ldmatrix.sync.aligned.m8n8.x4.shared.b16 {%0,%1,%2,%3}, [%4];"
                 : "=r"(r[0]), "=r"(r[1]), "=r"(r[2]), "=r"(r[3]) : "r"(addr));
}
__device__ __forceinline__ void mma_f16(float* c, const uint32_t* a, const uint32_t* b) {
    asm volatile(
        "mma.sync.aligned.m16n8k16.row.col.f32.f16.f16.f32 "
        "{%0,%1,%2,%3}, {%4,%5,%6,%7}, {%8,%9}, {%0,%1,%2,%3};"
        : "+f"(c[0]), "+f"(c[1]), "+f"(c[2]), "+f"(c[3])
        : "r"(a[0]), "r"(a[1]), "r"(a[2]), "r"(a[3]), "r"(b[0]), "r"(b[1]));
}

// ---------------- prep (straight fp32 -> fp16, standard layout) ----------------
__global__ void prep_x_kernel(const float* __restrict__ x) {
    const size_t n8 = (size_t)M_TOT * K_TOT / 8;
    for (size_t g = blockIdx.x * blockDim.x + threadIdx.x; g < n8;
         g += (size_t)gridDim.x * blockDim.x) {
        const float4 a = ((const float4*)(x + g * 8))[0];
        const float4 b = ((const float4*)(x + g * 8))[1];
        __half2 o[4];
        o[0] = __floats2half2_rn(a.x, a.y);
        o[1] = __floats2half2_rn(a.z, a.w);
        o[2] = __floats2half2_rn(b.x, b.y);
        o[3] = __floats2half2_rn(b.z, b.w);
        *(uint4*)(g_Xh + g * 8) = *(const uint4*)o;
    }
}

__global__ void build_w_kernel(const float* __restrict__ cb, const int* __restrict__ assign) {
    const int o = blockIdx.x;     // 0..4095
    const int j = threadIdx.x;    // 0..127
    __half* wrow = &g_Wh[(size_t)o * K_TOT];
#pragma unroll 1
    for (int s = 0; s < 32; s++) {
        const int code = __ldg(&assign[o * 32 + s]);
        wrow[s * 128 + j] = __float2half_rn(cb[((size_t)(s * 256 + code)) * 128 + j]);
    }
}

// SW128 swizzle for the cp.async store side (off = row*128 + col_bytes)
__device__ __forceinline__ uint32_t swz(uint32_t off) {
    return off ^ ((off >> 3) & 0x70);
}

// ---------------- GEMM ----------------
__global__ __launch_bounds__(128, 2) void pq_f16_gemm(float* __restrict__ out)
{
    const __half* __restrict__ A = g_Xh;
    const __half* __restrict__ B = g_Wh;

    extern __shared__ char smem[];
    const uint32_t sbase = smem_u32(smem);

    const int tid  = threadIdx.x;
    const int wid  = tid >> 5;       // 0..3
    const int lane = tid & 31;
    const int lq   = lane >> 2;
    const int lr   = lane & 3;
    const int sel  = lane >> 3;      // ldmatrix matrix selector 0..3
    const int lrow = lane & 7;       // row within 8x8 matrix

    // grid swizzle: 8x8 tile groups
    const int bid = blockIdx.x;
    const int grp = bid >> 6;
    const int r   = bid & 63;
    const int mt  = (grp & 7) * 8 + (r & 7);
    const int nt  = (grp >> 3) * 8 + (r >> 3);
    const int m0  = mt * BM;
    const int n0  = nt * BN;

    // warp tile 64x64 (2x2 warps)
    const int wm = (wid >> 1) * 64;
    const int wn = (wid & 1) * 64;

    float acc[4][8][4];
#pragma unroll
    for (int mi = 0; mi < 4; mi++)
#pragma unroll
        for (int ni = 0; ni < 8; ni++)
#pragma unroll
            for (int q = 0; q < 4; q++) acc[mi][ni][q] = 0.f;

    // ldmatrix per-lane components (within a stage):
    // addr = stagebase + rowbase + ((col + ko) ^ sx),  sx = (row&7)*16
    uint32_t a_base[4], a_sx[4], b_base[4], b_sx[4];
    const uint32_t a_col = (uint32_t)((sel >> 1) << 4);   // 0 or 16
    const uint32_t b_col = (uint32_t)((sel & 1) << 4);    // 0 or 16
#pragma unroll
    for (int mi = 0; mi < 4; mi++) {
        const int row = wm + mi * 16 + ((sel & 1) << 3) + lrow;
        a_base[mi] = (uint32_t)(row * 128);
        a_sx[mi]   = (uint32_t)((row & 7) * 16);
    }
#pragma unroll
    for (int np = 0; np < 4; np++) {
        const int n = wn + np * 16 + ((sel >> 1) << 3) + lrow;
        b_base[np] = (uint32_t)(n * 128);
        b_sx[np]   = (uint32_t)((n & 7) * 16);
    }

    // cp.async mapping: per operand 1024 x 16B, 128 threads -> 8 each
    const int l_row = tid >> 3;      // 0..15 (x8 passes)
    const int l_c   = tid & 7;       // 16B unit

    auto load_stage = [&](int chunk) {
        const int st = chunk % STAGES;
        const int k0 = chunk * BK;
        const uint32_t ab = sbase + st * A_STAGE_BYTES;
        const uint32_t bb = sbase + SM_B_OFF + st * B_STAGE_BYTES;
#pragma unroll
        for (int p = 0; p < 8; p++) {
            const int row = l_row + p * 16;
            const uint32_t so = swz(row * 128 + l_c * 16);
            cpa16(ab + so, A + (size_t)(m0 + row) * K_TOT + k0 + l_c * 8);
            cpa16(bb + so, B + (size_t)(n0 + row) * K_TOT + k0 + l_c * 8);
        }
    };

#pragma unroll
    for (int c = 0; c < STAGES - 1; c++) { load_stage(c); cp_commit(); }

#pragma unroll 1
    for (int i = 0; i < NCHUNK; i++) {
        cp_wait<1>();                // chunk i resident (i+1 may be in flight)
        __syncthreads();             // all warps done with the stage being reused
        if (i + STAGES - 1 < NCHUNK) load_stage(i + STAGES - 1);
        cp_commit();

        const int st = i % STAGES;
        const uint32_t ab = sbase + st * A_STAGE_BYTES;
        const uint32_t bb = sbase + SM_B_OFF + st * B_STAGE_BYTES;

        uint32_t af[2][4][4], bf[2][4][4];
        // prefetch k-step 0
#pragma unroll
        for (int mi = 0; mi < 4; mi++)
            ldsm4(af[0][mi], ab + a_base[mi] + (a_col ^ a_sx[mi]));
#pragma unroll
        for (int np = 0; np < 4; np++)
            ldsm4(bf[0][np], bb + b_base[np] + (b_col ^ b_sx[np]));

#pragma unroll
        for (int kg = 0; kg < 4; kg++) {
            const int cur = kg & 1, nxt = cur ^ 1;
            if (kg < 3) {
                const uint32_t ko = (uint32_t)((kg + 1) * 32);
#pragma unroll
                for (int mi = 0; mi < 4; mi++)
                    ldsm4(af[nxt][mi], ab + a_base[mi] + ((a_col + ko) ^ a_sx[mi]));
#pragma unroll
                for (int np = 0; np < 4; np++)
                    ldsm4(bf[nxt][np], bb + b_base[np] + ((b_col + ko) ^ b_sx[np]));
            }
#pragma unroll
            for (int mi = 0; mi < 4; mi++)
#pragma unroll
                for (int ni = 0; ni < 8; ni++)
                    mma_f16(acc[mi][ni], af[cur][mi], &bf[cur][ni >> 1][(ni & 1) * 2]);
        }
        __syncthreads();
    }

    // epilogue
#pragma unroll
    for (int mi = 0; mi < 4; mi++) {
#pragma unroll
        for (int ni = 0; ni < 8; ni++) {
            const int row0 = m0 + wm + mi * 16 + lq;
            const int col  = n0 + wn + ni * 8 + 2 * lr;
            *(float2*)&out[(size_t)row0 * N_TOT + col] =
                make_float2(acc[mi][ni][0], acc[mi][ni][1]);
            *(float2*)&out[(size_t)(row0 + 8) * N_TOT + col] =
                make_float2(acc[mi][ni][2], acc[mi][ni][3]);
        }
    }
}

extern "C" void kernel_launch(void* const* d_in, const int* in_sizes, int n_in,
                              void* d_out, int out_size) {
    const float* x         = (const float*)d_in[0];   // [4,2048,4096] fp32
    const float* codebooks = (const float*)d_in[1];   // [32,256,128] fp32
    const int*   assign    = (const int*)d_in[2];     // [4096,32] int32
    float*       out       = (float*)d_out;

    prep_x_kernel<<<4096, 256>>>(x);
    build_w_kernel<<<4096, 128>>>(codebooks, assign);

    cudaFuncSetAttribute(pq_f16_gemm,
                         cudaFuncAttributeMaxDynamicSharedMemorySize, SMEM_BYTES);
    pq_f16_gemm<<<(M_TOT / BM) * (N_TOT / BN), 128, SMEM_BYTES>>>(out);
}

// round 10
// speedup vs baseline: 2.5486x; 1.1050x over previous
#include <cuda_runtime.h>
#include <cuda_fp16.h>
#include <cstdint>

// PQLinear: out[8192,4096] = X[8192,4096] @ W^T (W gathered from PQ codebooks).
// R10: R9 + pipeline refinements:
//  - ONE __syncthreads per chunk (bottom sync removed; top sync of iter i+1
//    already orders compute(i) before any overwrite of stage i%3)
//  - chunk body order: wait -> sync -> ldsm k0 prefetch -> cp.async i+2 -> MMAs
//    (first-fragment LDS latency hides under cp.async issue)

#define M_TOT 8192
#define N_TOT 4096
#define K_TOT 4096
#define BM 128
#define BN 128
#define BK 64                         // halves per chunk (128 B rows)
#define STAGES 3
#define NCHUNK (K_TOT / BK)           // 64
#define A_STAGE_BYTES (BM * 128)      // 16384
#define B_STAGE_BYTES (BN * 128)      // 16384
#define SM_B_OFF (STAGES * A_STAGE_BYTES)
#define SMEM_BYTES (STAGES * (A_STAGE_BYTES + B_STAGE_BYTES))   // 98304

__device__ __half g_Xh[(size_t)M_TOT * K_TOT];   // 64 MB fp16 X
__device__ __half g_Wh[(size_t)N_TOT * K_TOT];   // 32 MB fp16 gathered W

// ---------------- helpers ----------------
__device__ __forceinline__ uint32_t smem_u32(const void* p) {
    uint32_t a;
    asm("{ .reg .u64 t; cvta.to.shared.u64 t, %1; cvt.u32.u64 %0, t; }" : "=r"(a) : "l"(p));
    return a;
}
__device__ __forceinline__ void cpa16(uint32_t saddr, const void* gaddr) {
    asm volatile("cp.async.cg.shared.global [%0], [%1], 16;" :: "r"(saddr), "l"(gaddr));
}
__device__ __forceinline__ void cp_commit() { asm volatile("cp.async.commit_group;" ::: "memory"); }
template <int N>
__device__ __forceinline__ void cp_wait() { asm volatile("cp.async.wait_group %0;" :: "n"(N) : "memory"); }

__device__ __forceinline__ void ldsm4(uint32_t* r, uint32_t addr) {
    asm volatile("ldmatrix.sync.aligned.m8n8.x4.shared.b16 {%0,%1,%2,%3}, [%4];"
                 : "=r"(r[0]), "=r"(r[1]), "=r"(r[2]), "=r"(r[3]) : "r"(addr));
}
__device__ __forceinline__ void mma_f16(float* c, const uint32_t* a, const uint32_t* b) {
    asm volatile(
        "mma.sync.aligned.m16n8k16.row.col.f32.f16.f16.f32 "
        "{%0,%1,%2,%3}, {%4,%5,%6,%7}, {%8,%9}, {%0,%1,%2,%3};"
        : "+f"(c[0]), "+f"(c[1]), "+f"(c[2]), "+f"(c[3])
        : "r"(a[0]), "r"(a[1]), "r"(a[2]), "r"(a[3]), "r"(b[0]), "r"(b[1]));
}

// ---------------- prep ----------------
__global__ void prep_x_kernel(const float* __restrict__ x) {
    const size_t n8 = (size_t)M_TOT * K_TOT / 8;
    for (size_t g = blockIdx.x * blockDim.x + threadIdx.x; g < n8;
         g += (size_t)gridDim.x * blockDim.x) {
        const float4 a = ((const float4*)(x + g * 8))[0];
        const float4 b = ((const float4*)(x + g * 8))[1];
        __half2 o[4];
        o[0] = __floats2half2_rn(a.x, a.y);
        o[1] = __floats2half2_rn(a.z, a.w);
        o[2] = __floats2half2_rn(b.x, b.y);
        o[3] = __floats2half2_rn(b.z, b.w);
        *(uint4*)(g_Xh + g * 8) = *(const uint4*)o;
    }
}

__global__ void build_w_kernel(const float* __restrict__ cb, const int* __restrict__ assign) {
    const int o = blockIdx.x;     // 0..4095
    const int j = threadIdx.x;    // 0..127
    __half* wrow = &g_Wh[(size_t)o * K_TOT];
#pragma unroll 1
    for (int s = 0; s < 32; s++) {
        const int code = __ldg(&assign[o * 32 + s]);
        wrow[s * 128 + j] = __float2half_rn(cb[((size_t)(s * 256 + code)) * 128 + j]);
    }
}

// SW128 swizzle for the cp.async store side (off = row*128 + col_bytes)
__device__ __forceinline__ uint32_t swz(uint32_t off) {
    return off ^ ((off >> 3) & 0x70);
}

// ---------------- GEMM ----------------
__global__ __launch_bounds__(128, 2) void pq_f16_gemm(float* __restrict__ out)
{
    const __half* __restrict__ A = g_Xh;
    const __half* __restrict__ B = g_Wh;

    extern __shared__ char smem[];
    const uint32_t sbase = smem_u32(smem);

    const int tid  = threadIdx.x;
    const int wid  = tid >> 5;       // 0..3
    const int lane = tid & 31;
    const int lq   = lane >> 2;
    const int lr   = lane & 3;
    const int sel  = lane >> 3;      // ldmatrix matrix selector 0..3
    const int lrow = lane & 7;

    // grid swizzle: 8x8 tile groups
    const int bid = blockIdx.x;
    const int grp = bid >> 6;
    const int r   = bid & 63;
    const int mt  = (grp & 7) * 8 + (r & 7);
    const int nt  = (grp >> 3) * 8 + (r >> 3);
    const int m0  = mt * BM;
    const int n0  = nt * BN;

    // warp tile 64x64 (2x2 warps)
    const int wm = (wid >> 1) * 64;
    const int wn = (wid & 1) * 64;

    float acc[4][8][4];
#pragma unroll
    for (int mi = 0; mi < 4; mi++)
#pragma unroll
        for (int ni = 0; ni < 8; ni++)
#pragma unroll
            for (int q = 0; q < 4; q++) acc[mi][ni][q] = 0.f;

    // ldmatrix addr = stagebase + rowbase + ((col + ko) ^ sx),  sx=(row&7)*16
    uint32_t a_base[4], a_sx[4], b_base[4], b_sx[4];
    const uint32_t a_col = (uint32_t)((sel >> 1) << 4);
    const uint32_t b_col = (uint32_t)((sel & 1) << 4);
#pragma unroll
    for (int mi = 0; mi < 4; mi++) {
        const int row = wm + mi * 16 + ((sel & 1) << 3) + lrow;
        a_base[mi] = (uint32_t)(row * 128);
        a_sx[mi]   = (uint32_t)((row & 7) * 16);
    }
#pragma unroll
    for (int np = 0; np < 4; np++) {
        const int n = wn + np * 16 + ((sel >> 1) << 3) + lrow;
        b_base[np] = (uint32_t)(n * 128);
        b_sx[np]   = (uint32_t)((n & 7) * 16);
    }

    // cp.async mapping: per operand 1024 x 16B, 128 threads -> 8 each
    const int l_row = tid >> 3;
    const int l_c   = tid & 7;

    auto load_stage = [&](int chunk) {
        const int st = chunk % STAGES;
        const int k0 = chunk * BK;
        const uint32_t ab = sbase + st * A_STAGE_BYTES;
        const uint32_t bb = sbase + SM_B_OFF + st * B_STAGE_BYTES;
#pragma unroll
        for (int p = 0; p < 8; p++) {
            const int row = l_row + p * 16;
            const uint32_t so = swz(row * 128 + l_c * 16);
            cpa16(ab + so, A + (size_t)(m0 + row) * K_TOT + k0 + l_c * 8);
            cpa16(bb + so, B + (size_t)(n0 + row) * K_TOT + k0 + l_c * 8);
        }
    };

#pragma unroll
    for (int c = 0; c < STAGES - 1; c++) { load_stage(c); cp_commit(); }

#pragma unroll 1
    for (int i = 0; i < NCHUNK; i++) {
        cp_wait<1>();                // chunk i resident (i+1 may be in flight)
        __syncthreads();             // orders compute(i-1) before overwrite below

        const int st = i % STAGES;
        const uint32_t ab = sbase + st * A_STAGE_BYTES;
        const uint32_t bb = sbase + SM_B_OFF + st * B_STAGE_BYTES;

        uint32_t af[2][4][4], bf[2][4][4];
        // prefetch k-step 0 fragments first (latency hides under cp.async issue)
#pragma unroll
        for (int mi = 0; mi < 4; mi++)
            ldsm4(af[0][mi], ab + a_base[mi] + (a_col ^ a_sx[mi]));
#pragma unroll
        for (int np = 0; np < 4; np++)
            ldsm4(bf[0][np], bb + b_base[np] + (b_col ^ b_sx[np]));

        if (i + STAGES - 1 < NCHUNK) load_stage(i + STAGES - 1);
        cp_commit();

#pragma unroll
        for (int kg = 0; kg < 4; kg++) {
            const int cur = kg & 1, nxt = cur ^ 1;
            if (kg < 3) {
                const uint32_t ko = (uint32_t)((kg + 1) * 32);
#pragma unroll
                for (int mi = 0; mi < 4; mi++)
                    ldsm4(af[nxt][mi], ab + a_base[mi] + ((a_col + ko) ^ a_sx[mi]));
#pragma unroll
                for (int np = 0; np < 4; np++)
                    ldsm4(bf[nxt][np], bb + b_base[np] + ((b_col + ko) ^ b_sx[np]));
            }
#pragma unroll
            for (int mi = 0; mi < 4; mi++)
#pragma unroll
                for (int ni = 0; ni < 8; ni++)
                    mma_f16(acc[mi][ni], af[cur][mi], &bf[cur][ni >> 1][(ni & 1) * 2]);
        }
        // no bottom sync: next iteration's top sync provides the ordering
    }

    // epilogue
#pragma unroll
    for (int mi = 0; mi < 4; mi++) {
#pragma unroll
        for (int ni = 0; ni < 8; ni++) {
            const int row0 = m0 + wm + mi * 16 + lq;
            const int col  = n0 + wn + ni * 8 + 2 * lr;
            *(float2*)&out[(size_t)row0 * N_TOT + col] =
                make_float2(acc[mi][ni][0], acc[mi][ni][1]);
            *(float2*)&out[(size_t)(row0 + 8) * N_TOT + col] =
                make_float2(acc[mi][ni][2], acc[mi][ni][3]);
        }
    }
}

extern "C" void kernel_launch(void* const* d_in, const int* in_sizes, int n_in,
                              void* d_out, int out_size) {
    const float* x         = (const float*)d_in[0];   // [4,2048,4096] fp32
    const float* codebooks = (const float*)d_in[1];   // [32,256,128] fp32
    const int*   assign    = (const int*)d_in[2];     // [4096,32] int32
    float*       out       = (float*)d_out;

    prep_x_kernel<<<4096, 256>>>(x);
    build_w_kernel<<<4096, 128>>>(codebooks, assign);

    cudaFuncSetAttribute(pq_f16_gemm,
                         cudaFuncAttributeMaxDynamicSharedMemorySize, SMEM_BYTES);
    pq_f16_gemm<<<(M_TOT / BM) * (N_TOT / BN), 128, SMEM_BYTES>>>(out);
}

// round 12
// speedup vs baseline: 2.7318x; 1.0719x over previous
#include <cuda_runtime.h>
#include <cuda_fp16.h>
#include <cstdint>

// PQLinear: out[8192,4096] = X[8192,4096] @ W^T (W gathered from PQ codebooks).
// R12 (= R11 with the compile fix): R10 GEMM + edge fixes:
//  - build_w parallelized: one warp per (o,s) pair, coalesced 512B read /
//    256B write, no serial dependent-gather loop
//  - GEMM: incremental stage index (no i%3 mul), carried global base pointers

#define M_TOT 8192
#define N_TOT 4096
#define K_TOT 4096
#define BM 128
#define BN 128
#define BK 64                         // halves per chunk (128 B rows)
#define STAGES 3
#define NCHUNK (K_TOT / BK)           // 64
#define A_STAGE_BYTES (BM * 128)      // 16384
#define B_STAGE_BYTES (BN * 128)      // 16384
#define SM_B_OFF (STAGES * A_STAGE_BYTES)
#define SMEM_BYTES (STAGES * (A_STAGE_BYTES + B_STAGE_BYTES))   // 98304

__device__ __half g_Xh[(size_t)M_TOT * K_TOT];   // 64 MB fp16 X
__device__ __half g_Wh[(size_t)N_TOT * K_TOT];   // 32 MB fp16 gathered W

// ---------------- helpers ----------------
__device__ __forceinline__ uint32_t smem_u32(const void* p) {
    uint32_t a;
    asm("{ .reg .u64 t; cvta.to.shared.u64 t, %1; cvt.u32.u64 %0, t; }" : "=r"(a) : "l"(p));
    return a;
}
__device__ __forceinline__ void cpa16(uint32_t saddr, const void* gaddr) {
    asm volatile("cp.async.cg.shared.global [%0], [%1], 16;" :: "r"(saddr), "l"(gaddr));
}
__device__ __forceinline__ void cp_commit() { asm volatile("cp.async.commit_group;" ::: "memory"); }
template <int N>
__device__ __forceinline__ void cp_wait() { asm volatile("cp.async.wait_group %0;" :: "n"(N) : "memory"); }

__device__ __forceinline__ void ldsm4(uint32_t* r, uint32_t addr) {
    asm volatile("ldmatrix.sync.aligned.m8n8.x4.shared.b16 {%0,%1,%2,%3}, [%4];"
                 : "=r"(r[0]), "=r"(r[1]), "=r"(r[2]), "=r"(r[3]) : "r"(addr));
}
__device__ __forceinline__ void mma_f16(float* c, const uint32_t* a, const uint32_t* b) {
    asm volatile(
        "mma.sync.aligned.m16n8k16.row.col.f32.f16.f16.f32 "
        "{%0,%1,%2,%3}, {%4,%5,%6,%7}, {%8,%9}, {%0,%1,%2,%3};"
        : "+f"(c[0]), "+f"(c[1]), "+f"(c[2]), "+f"(c[3])
        : "r"(a[0]), "r"(a[1]), "r"(a[2]), "r"(a[3]), "r"(b[0]), "r"(b[1]));
}

// ---------------- prep ----------------
__global__ void prep_x_kernel(const float* __restrict__ x) {
    const size_t n8 = (size_t)M_TOT * K_TOT / 8;
    for (size_t g = blockIdx.x * blockDim.x + threadIdx.x; g < n8;
         g += (size_t)gridDim.x * blockDim.x) {
        const float4 a = ((const float4*)(x + g * 8))[0];
        const float4 b = ((const float4*)(x + g * 8))[1];
        __half2 o[4];
        o[0] = __floats2half2_rn(a.x, a.y);
        o[1] = __floats2half2_rn(a.z, a.w);
        o[2] = __floats2half2_rn(b.x, b.y);
        o[3] = __floats2half2_rn(b.z, b.w);
        *(uint4*)(g_Xh + g * 8) = *(const uint4*)o;
    }
}

// one warp per (o, s): lane reads float4 (512B/warp), writes 2x half2 (256B/warp)
__global__ void build_w_kernel(const float* __restrict__ cb, const int* __restrict__ assign) {
    const int gw   = (blockIdx.x * blockDim.x + threadIdx.x) >> 5;  // global warp
    const int lane = threadIdx.x & 31;
    if (gw >= N_TOT * 32) return;
    const int o = gw >> 5;          // output row
    const int s = gw & 31;          // subvector
    const int code = __ldg(&assign[o * 32 + s]);
    const float4 v = *(const float4*)(cb + ((size_t)(s * 256 + code)) * 128 + lane * 4);
    __half2 h[2];
    h[0] = __floats2half2_rn(v.x, v.y);
    h[1] = __floats2half2_rn(v.z, v.w);
    *(uint2*)(g_Wh + (size_t)o * K_TOT + s * 128 + lane * 4) = *(const uint2*)h;
}

// SW128 swizzle for the cp.async store side (off = row*128 + col_bytes)
__device__ __forceinline__ uint32_t swz(uint32_t off) {
    return off ^ ((off >> 3) & 0x70);
}

// ---------------- GEMM ----------------
__global__ __launch_bounds__(128, 2) void pq_f16_gemm(float* __restrict__ out)
{
    extern __shared__ char smem[];
    const uint32_t sbase = smem_u32(smem);

    const int tid  = threadIdx.x;
    const int wid  = tid >> 5;       // 0..3
    const int lane = tid & 31;
    const int lq   = lane >> 2;
    const int lr   = lane & 3;
    const int sel  = lane >> 3;      // ldmatrix matrix selector 0..3
    const int lrow = lane & 7;

    // grid swizzle: 8x8 tile groups
    const int bid = blockIdx.x;
    const int grp = bid >> 6;
    const int r   = bid & 63;
    const int mt  = (grp & 7) * 8 + (r & 7);
    const int nt  = (grp >> 3) * 8 + (r >> 3);
    const int m0  = mt * BM;
    const int n0  = nt * BN;

    // warp tile 64x64 (2x2 warps)
    const int wm = (wid >> 1) * 64;
    const int wn = (wid & 1) * 64;

    float acc[4][8][4];
#pragma unroll
    for (int mi = 0; mi < 4; mi++)
#pragma unroll
        for (int ni = 0; ni < 8; ni++)
#pragma unroll
            for (int q = 0; q < 4; q++) acc[mi][ni][q] = 0.f;

    // ldmatrix addr = stagebase + rowbase + ((col + ko) ^ sx),  sx=(row&7)*16
    uint32_t a_base[4], a_sx[4], b_base[4], b_sx[4];
    const uint32_t a_col = (uint32_t)((sel >> 1) << 4);
    const uint32_t b_col = (uint32_t)((sel & 1) << 4);
#pragma unroll
    for (int mi = 0; mi < 4; mi++) {
        const int row = wm + mi * 16 + ((sel & 1) << 3) + lrow;
        a_base[mi] = (uint32_t)(row * 128);
        a_sx[mi]   = (uint32_t)((row & 7) * 16);
    }
#pragma unroll
    for (int np = 0; np < 4; np++) {
        const int n = wn + np * 16 + ((sel >> 1) << 3) + lrow;
        b_base[np] = (uint32_t)(n * 128);
        b_sx[np]   = (uint32_t)((n & 7) * 16);
    }

    // cp.async mapping: per operand 1024 x 16B, 128 threads -> 8 each
    const int l_row = tid >> 3;
    const int l_c   = tid & 7;

    // carried global pointers (incremented by BK halves per chunk)
    const __half* aptr = g_Xh + (size_t)(m0 + l_row) * K_TOT + l_c * 8;
    const __half* bptr = g_Wh + (size_t)(n0 + l_row) * K_TOT + l_c * 8;
    const uint32_t so_base[8] = {
        swz((l_row +   0) * 128 + l_c * 16), swz((l_row +  16) * 128 + l_c * 16),
        swz((l_row +  32) * 128 + l_c * 16), swz((l_row +  48) * 128 + l_c * 16),
        swz((l_row +  64) * 128 + l_c * 16), swz((l_row +  80) * 128 + l_c * 16),
        swz((l_row +  96) * 128 + l_c * 16), swz((l_row + 112) * 128 + l_c * 16)};

    auto load_stage = [&](int st, const __half* ap, const __half* bp) {
        const uint32_t ab = sbase + st * A_STAGE_BYTES;
        const uint32_t bb = sbase + SM_B_OFF + st * B_STAGE_BYTES;
#pragma unroll
        for (int p = 0; p < 8; p++) {
            cpa16(ab + so_base[p], ap + (size_t)(p * 16) * K_TOT);
            cpa16(bb + so_base[p], bp + (size_t)(p * 16) * K_TOT);
        }
    };

    const __half* ald = aptr;   // load cursor (chunk to fetch)
    const __half* bld = bptr;
#pragma unroll
    for (int c = 0; c < STAGES - 1; c++) {
        load_stage(c, ald, bld);
        cp_commit();
        ald += BK; bld += BK;
    }

    int st = 0;                 // stage of chunk i
    int st_ld = STAGES - 1;     // stage for the next load
#pragma unroll 1
    for (int i = 0; i < NCHUNK; i++) {
        cp_wait<1>();                // chunk i resident (i+1 may be in flight)
        __syncthreads();             // orders compute(i-1) before overwrite below

        const uint32_t ab = sbase + st * A_STAGE_BYTES;
        const uint32_t bb = sbase + SM_B_OFF + st * B_STAGE_BYTES;

        uint32_t af[2][4][4], bf[2][4][4];
#pragma unroll
        for (int mi = 0; mi < 4; mi++)
            ldsm4(af[0][mi], ab + a_base[mi] + (a_col ^ a_sx[mi]));
#pragma unroll
        for (int np = 0; np < 4; np++)
            ldsm4(bf[0][np], bb + b_base[np] + (b_col ^ b_sx[np]));

        if (i + STAGES - 1 < NCHUNK) {
            load_stage(st_ld, ald, bld);
            ald += BK; bld += BK;
        }
        cp_commit();

#pragma unroll
        for (int kg = 0; kg < 4; kg++) {
            const int cur = kg & 1, nxt = cur ^ 1;
            if (kg < 3) {
                const uint32_t ko = (uint32_t)((kg + 1) * 32);
#pragma unroll
                for (int mi = 0; mi < 4; mi++)
                    ldsm4(af[nxt][mi], ab + a_base[mi] + ((a_col + ko) ^ a_sx[mi]));
#pragma unroll
                for (int np = 0; np < 4; np++)
                    ldsm4(bf[nxt][np], bb + b_base[np] + ((b_col + ko) ^ b_sx[np]));
            }
#pragma unroll
            for (int mi = 0; mi < 4; mi++)
#pragma unroll
                for (int ni = 0; ni < 8; ni++)
                    mma_f16(acc[mi][ni], af[cur][mi], &bf[cur][ni >> 1][(ni & 1) * 2]);
        }
        st    = (st    == STAGES - 1) ? 0 : st + 1;
        st_ld = (st_ld == STAGES - 1) ? 0 : st_ld + 1;
    }

    // epilogue
#pragma unroll
    for (int mi = 0; mi < 4; mi++) {
#pragma unroll
        for (int ni = 0; ni < 8; ni++) {
            const int row0 = m0 + wm + mi * 16 + lq;
            const int col  = n0 + wn + ni * 8 + 2 * lr;
            *(float2*)&out[(size_t)row0 * N_TOT + col] =
                make_float2(acc[mi][ni][0], acc[mi][ni][1]);
            *(float2*)&out[(size_t)(row0 + 8) * N_TOT + col] =
                make_float2(acc[mi][ni][2], acc[mi][ni][3]);
        }
    }
}

extern "C" void kernel_launch(void* const* d_in, const int* in_sizes, int n_in,
                              void* d_out, int out_size) {
    const float* x         = (const float*)d_in[0];   // [4,2048,4096] fp32
    const float* codebooks = (const float*)d_in[1];   // [32,256,128] fp32
    const int*   assign    = (const int*)d_in[2];     // [4096,32] int32
    float*       out       = (float*)d_out;

    prep_x_kernel<<<4096, 256>>>(x);
    build_w_kernel<<<(N_TOT * 32 * 32) / 256, 256>>>(codebooks, assign);

    cudaFuncSetAttribute(pq_f16_gemm,
                         cudaFuncAttributeMaxDynamicSharedMemorySize, SMEM_BYTES);
    pq_f16_gemm<<<(M_TOT / BM) * (N_TOT / BN), 128, SMEM_BYTES>>>(out);
}

// round 13
// speedup vs baseline: 2.7354x; 1.0013x over previous
#include <cuda_runtime.h>
#include <cuda_fp16.h>
#include <cstdint>

// PQLinear: out[8192,4096] = X[8192,4096] @ W^T (W gathered from PQ codebooks).
// R13: R12 GEMM untouched (~90% of mma.sync ceiling). Prep kernels FUSED into
// one launch: build_w (L2/latency-bound) overlaps under prep_x (DRAM-bound).

#define M_TOT 8192
#define N_TOT 4096
#define K_TOT 4096
#define BM 128
#define BN 128
#define BK 64                         // halves per chunk (128 B rows)
#define STAGES 3
#define NCHUNK (K_TOT / BK)           // 64
#define A_STAGE_BYTES (BM * 128)      // 16384
#define B_STAGE_BYTES (BN * 128)      // 16384
#define SM_B_OFF (STAGES * A_STAGE_BYTES)
#define SMEM_BYTES (STAGES * (A_STAGE_BYTES + B_STAGE_BYTES))   // 98304

#define W_BLOCKS 16384                // build_w: 131072 warps, 8 warps/block
#define X_BLOCKS 4096                 // prep_x grid-stride portion

__device__ __half g_Xh[(size_t)M_TOT * K_TOT];   // 64 MB fp16 X
__device__ __half g_Wh[(size_t)N_TOT * K_TOT];   // 32 MB fp16 gathered W

// ---------------- helpers ----------------
__device__ __forceinline__ uint32_t smem_u32(const void* p) {
    uint32_t a;
    asm("{ .reg .u64 t; cvta.to.shared.u64 t, %1; cvt.u32.u64 %0, t; }" : "=r"(a) : "l"(p));
    return a;
}
__device__ __forceinline__ void cpa16(uint32_t saddr, const void* gaddr) {
    asm volatile("cp.async.cg.shared.global [%0], [%1], 16;" :: "r"(saddr), "l"(gaddr));
}
__device__ __forceinline__ void cp_commit() { asm volatile("cp.async.commit_group;" ::: "memory"); }
template <int N>
__device__ __forceinline__ void cp_wait() { asm volatile("cp.async.wait_group %0;" :: "n"(N) : "memory"); }

__device__ __forceinline__ void ldsm4(uint32_t* r, uint32_t addr) {
    asm volatile("ldmatrix.sync.aligned.m8n8.x4.shared.b16 {%0,%1,%2,%3}, [%4];"
                 : "=r"(r[0]), "=r"(r[1]), "=r"(r[2]), "=r"(r[3]) : "r"(addr));
}
__device__ __forceinline__ void mma_f16(float* c, const uint32_t* a, const uint32_t* b) {
    asm volatile(
        "mma.sync.aligned.m16n8k16.row.col.f32.f16.f16.f32 "
        "{%0,%1,%2,%3}, {%4,%5,%6,%7}, {%8,%9}, {%0,%1,%2,%3};"
        : "+f"(c[0]), "+f"(c[1]), "+f"(c[2]), "+f"(c[3])
        : "r"(a[0]), "r"(a[1]), "r"(a[2]), "r"(a[3]), "r"(b[0]), "r"(b[1]));
}

// ---------------- fused prep: W gather (blocks [0, W_BLOCKS)) + X convert ----
__global__ void prep_fused_kernel(const float* __restrict__ x,
                                  const float* __restrict__ cb,
                                  const int* __restrict__ assign) {
    if (blockIdx.x < W_BLOCKS) {
        // build W: one warp per (o, s); lane reads float4, writes 2x half2
        const int gw   = (blockIdx.x * blockDim.x + threadIdx.x) >> 5;
        const int lane = threadIdx.x & 31;
        const int o = gw >> 5;          // output row
        const int s = gw & 31;          // subvector
        const int code = __ldg(&assign[o * 32 + s]);
        const float4 v = *(const float4*)(cb + ((size_t)(s * 256 + code)) * 128 + lane * 4);
        __half2 h[2];
        h[0] = __floats2half2_rn(v.x, v.y);
        h[1] = __floats2half2_rn(v.z, v.w);
        *(uint2*)(g_Wh + (size_t)o * K_TOT + s * 128 + lane * 4) = *(const uint2*)h;
    } else {
        // convert X: grid-stride over 8-float groups
        const size_t n8 = (size_t)M_TOT * K_TOT / 8;
        const size_t tid0 = (size_t)(blockIdx.x - W_BLOCKS) * blockDim.x + threadIdx.x;
        const size_t stride = (size_t)X_BLOCKS * blockDim.x;
        for (size_t g = tid0; g < n8; g += stride) {
            const float4 a = ((const float4*)(x + g * 8))[0];
            const float4 b = ((const float4*)(x + g * 8))[1];
            __half2 o[4];
            o[0] = __floats2half2_rn(a.x, a.y);
            o[1] = __floats2half2_rn(a.z, a.w);
            o[2] = __floats2half2_rn(b.x, b.y);
            o[3] = __floats2half2_rn(b.z, b.w);
            *(uint4*)(g_Xh + g * 8) = *(const uint4*)o;
        }
    }
}

// SW128 swizzle for the cp.async store side (off = row*128 + col_bytes)
__device__ __forceinline__ uint32_t swz(uint32_t off) {
    return off ^ ((off >> 3) & 0x70);
}

// ---------------- GEMM (unchanged from R12) ----------------
__global__ __launch_bounds__(128, 2) void pq_f16_gemm(float* __restrict__ out)
{
    extern __shared__ char smem[];
    const uint32_t sbase = smem_u32(smem);

    const int tid  = threadIdx.x;
    const int wid  = tid >> 5;       // 0..3
    const int lane = tid & 31;
    const int lq   = lane >> 2;
    const int lr   = lane & 3;
    const int sel  = lane >> 3;      // ldmatrix matrix selector 0..3
    const int lrow = lane & 7;

    // grid swizzle: 8x8 tile groups
    const int bid = blockIdx.x;
    const int grp = bid >> 6;
    const int r   = bid & 63;
    const int mt  = (grp & 7) * 8 + (r & 7);
    const int nt  = (grp >> 3) * 8 + (r >> 3);
    const int m0  = mt * BM;
    const int n0  = nt * BN;

    // warp tile 64x64 (2x2 warps)
    const int wm = (wid >> 1) * 64;
    const int wn = (wid & 1) * 64;

    float acc[4][8][4];
#pragma unroll
    for (int mi = 0; mi < 4; mi++)
#pragma unroll
        for (int ni = 0; ni < 8; ni++)
#pragma unroll
            for (int q = 0; q < 4; q++) acc[mi][ni][q] = 0.f;

    // ldmatrix addr = stagebase + rowbase + ((col + ko) ^ sx),  sx=(row&7)*16
    uint32_t a_base[4], a_sx[4], b_base[4], b_sx[4];
    const uint32_t a_col = (uint32_t)((sel >> 1) << 4);
    const uint32_t b_col = (uint32_t)((sel & 1) << 4);
#pragma unroll
    for (int mi = 0; mi < 4; mi++) {
        const int row = wm + mi * 16 + ((sel & 1) << 3) + lrow;
        a_base[mi] = (uint32_t)(row * 128);
        a_sx[mi]   = (uint32_t)((row & 7) * 16);
    }
#pragma unroll
    for (int np = 0; np < 4; np++) {
        const int n = wn + np * 16 + ((sel >> 1) << 3) + lrow;
        b_base[np] = (uint32_t)(n * 128);
        b_sx[np]   = (uint32_t)((n & 7) * 16);
    }

    // cp.async mapping: per operand 1024 x 16B, 128 threads -> 8 each
    const int l_row = tid >> 3;
    const int l_c   = tid & 7;

    const __half* aptr = g_Xh + (size_t)(m0 + l_row) * K_TOT + l_c * 8;
    const __half* bptr = g_Wh + (size_t)(n0 + l_row) * K_TOT + l_c * 8;
    const uint32_t so_base[8] = {
        swz((l_row +   0) * 128 + l_c * 16), swz((l_row +  16) * 128 + l_c * 16),
        swz((l_row +  32) * 128 + l_c * 16), swz((l_row +  48) * 128 + l_c * 16),
        swz((l_row +  64) * 128 + l_c * 16), swz((l_row +  80) * 128 + l_c * 16),
        swz((l_row +  96) * 128 + l_c * 16), swz((l_row + 112) * 128 + l_c * 16)};

    auto load_stage = [&](int st, const __half* ap, const __half* bp) {
        const uint32_t ab = sbase + st * A_STAGE_BYTES;
        const uint32_t bb = sbase + SM_B_OFF + st * B_STAGE_BYTES;
#pragma unroll
        for (int p = 0; p < 8; p++) {
            cpa16(ab + so_base[p], ap + (size_t)(p * 16) * K_TOT);
            cpa16(bb + so_base[p], bp + (size_t)(p * 16) * K_TOT);
        }
    };

    const __half* ald = aptr;
    const __half* bld = bptr;
#pragma unroll
    for (int c = 0; c < STAGES - 1; c++) {
        load_stage(c, ald, bld);
        cp_commit();
        ald += BK; bld += BK;
    }

    int st = 0;
    int st_ld = STAGES - 1;
#pragma unroll 1
    for (int i = 0; i < NCHUNK; i++) {
        cp_wait<1>();
        __syncthreads();

        const uint32_t ab = sbase + st * A_STAGE_BYTES;
        const uint32_t bb = sbase + SM_B_OFF + st * B_STAGE_BYTES;

        uint32_t af[2][4][4], bf[2][4][4];
#pragma unroll
        for (int mi = 0; mi < 4; mi++)
            ldsm4(af[0][mi], ab + a_base[mi] + (a_col ^ a_sx[mi]));
#pragma unroll
        for (int np = 0; np < 4; np++)
            ldsm4(bf[0][np], bb + b_base[np] + (b_col ^ b_sx[np]));

        if (i + STAGES - 1 < NCHUNK) {
            load_stage(st_ld, ald, bld);
            ald += BK; bld += BK;
        }
        cp_commit();

#pragma unroll
        for (int kg = 0; kg < 4; kg++) {
            const int cur = kg & 1, nxt = cur ^ 1;
            if (kg < 3) {
                const uint32_t ko = (uint32_t)((kg + 1) * 32);
#pragma unroll
                for (int mi = 0; mi < 4; mi++)
                    ldsm4(af[nxt][mi], ab + a_base[mi] + ((a_col + ko) ^ a_sx[mi]));
#pragma unroll
                for (int np = 0; np < 4; np++)
                    ldsm4(bf[nxt][np], bb + b_base[np] + ((b_col + ko) ^ b_sx[np]));
            }
#pragma unroll
            for (int mi = 0; mi < 4; mi++)
#pragma unroll
                for (int ni = 0; ni < 8; ni++)
                    mma_f16(acc[mi][ni], af[cur][mi], &bf[cur][ni >> 1][(ni & 1) * 2]);
        }
        st    = (st    == STAGES - 1) ? 0 : st + 1;
        st_ld = (st_ld == STAGES - 1) ? 0 : st_ld + 1;
    }

    // epilogue
#pragma unroll
    for (int mi = 0; mi < 4; mi++) {
#pragma unroll
        for (int ni = 0; ni < 8; ni++) {
            const int row0 = m0 + wm + mi * 16 + lq;
            const int col  = n0 + wn + ni * 8 + 2 * lr;
            *(float2*)&out[(size_t)row0 * N_TOT + col] =
                make_float2(acc[mi][ni][0], acc[mi][ni][1]);
            *(float2*)&out[(size_t)(row0 + 8) * N_TOT + col] =
                make_float2(acc[mi][ni][2], acc[mi][ni][3]);
        }
    }
}

extern "C" void kernel_launch(void* const* d_in, const int* in_sizes, int n_in,
                              void* d_out, int out_size) {
    const float* x         = (const float*)d_in[0];   // [4,2048,4096] fp32
    const float* codebooks = (const float*)d_in[1];   // [32,256,128] fp32
    const int*   assign    = (const int*)d_in[2];     // [4096,32] int32
    float*       out       = (float*)d_out;

    prep_fused_kernel<<<W_BLOCKS + X_BLOCKS, 256>>>(x, codebooks, assign);

    cudaFuncSetAttribute(pq_f16_gemm,
                         cudaFuncAttributeMaxDynamicSharedMemorySize, SMEM_BYTES);
    pq_f16_gemm<<<(M_TOT / BM) * (N_TOT / BN), 128, SMEM_BYTES>>>(out);
}

// round 14
// speedup vs baseline: 2.8515x; 1.0425x over previous
#include <cuda_runtime.h>
#include <cuda_fp16.h>
#include <cstdint>

// PQLinear: out[8192,4096] = X[8192,4096] @ W^T (W gathered from PQ codebooks).
// R14: vs R13:
//  - GEMM: cross-chunk k0 fragment prefetch (next chunk's first fragments load
//    under the current chunk's last MMA octet; cp_wait moved mid-chunk where
//    chunk i+1 residency is provable) -> removes the chunk-start ldsm bubble
//  - prep: W gather interleaved with X convert by block index (bid%3), W warps
//    do 8 (o,s) pairs each (MLP=8) -> W hides fully under X's DRAM streaming

#define M_TOT 8192
#define N_TOT 4096
#define K_TOT 4096
#define BM 128
#define BN 128
#define BK 64                         // halves per chunk (128 B rows)
#define STAGES 3
#define NCHUNK (K_TOT / BK)           // 64
#define A_STAGE_BYTES (BM * 128)      // 16384
#define B_STAGE_BYTES (BN * 128)      // 16384
#define SM_B_OFF (STAGES * A_STAGE_BYTES)
#define SMEM_BYTES (STAGES * (A_STAGE_BYTES + B_STAGE_BYTES))   // 98304

__device__ __half g_Xh[(size_t)M_TOT * K_TOT];   // 64 MB fp16 X
__device__ __half g_Wh[(size_t)N_TOT * K_TOT];   // 32 MB fp16 gathered W

// ---------------- helpers ----------------
__device__ __forceinline__ uint32_t smem_u32(const void* p) {
    uint32_t a;
    asm("{ .reg .u64 t; cvta.to.shared.u64 t, %1; cvt.u32.u64 %0, t; }" : "=r"(a) : "l"(p));
    return a;
}
__device__ __forceinline__ void cpa16(uint32_t saddr, const void* gaddr) {
    asm volatile("cp.async.cg.shared.global [%0], [%1], 16;" :: "r"(saddr), "l"(gaddr));
}
__device__ __forceinline__ void cp_commit() { asm volatile("cp.async.commit_group;" ::: "memory"); }
template <int N>
__device__ __forceinline__ void cp_wait() { asm volatile("cp.async.wait_group %0;" :: "n"(N) : "memory"); }

__device__ __forceinline__ void ldsm4(uint32_t* r, uint32_t addr) {
    asm volatile("ldmatrix.sync.aligned.m8n8.x4.shared.b16 {%0,%1,%2,%3}, [%4];"
                 : "=r"(r[0]), "=r"(r[1]), "=r"(r[2]), "=r"(r[3]) : "r"(addr));
}
__device__ __forceinline__ void mma_f16(float* c, const uint32_t* a, const uint32_t* b) {
    asm volatile(
        "mma.sync.aligned.m16n8k16.row.col.f32.f16.f16.f32 "
        "{%0,%1,%2,%3}, {%4,%5,%6,%7}, {%8,%9}, {%0,%1,%2,%3};"
        : "+f"(c[0]), "+f"(c[1]), "+f"(c[2]), "+f"(c[3])
        : "r"(a[0]), "r"(a[1]), "r"(a[2]), "r"(a[3]), "r"(b[0]), "r"(b[1]));
}

// ---------------- fused prep, interleaved by bid%3 ----------------
// grid = 6144 blocks x 256 thr: bid%3==2 -> W gather (2048 blocks), else X (4096)
__global__ void prep_fused_kernel(const float* __restrict__ x,
                                  const float* __restrict__ cb,
                                  const int* __restrict__ assign) {
    const int bid = blockIdx.x;
    const int m3  = bid % 3;
    if (m3 == 2) {
        // W: block wi covers 64 (o,s) pairs; each warp 8 pairs (independent -> MLP)
        const int wi   = bid / 3;                 // 0..2047
        const int warp = threadIdx.x >> 5;
        const int lane = threadIdx.x & 31;
        const int base = wi * 64 + warp * 8;
#pragma unroll
        for (int it = 0; it < 8; it++) {
            const int gw = base + it;
            const int o = gw >> 5;
            const int s = gw & 31;
            const int code = __ldg(&assign[o * 32 + s]);
            const float4 v = *(const float4*)(cb + ((size_t)(s * 256 + code)) * 128 + lane * 4);
            __half2 h[2];
            h[0] = __floats2half2_rn(v.x, v.y);
            h[1] = __floats2half2_rn(v.z, v.w);
            *(uint2*)(g_Wh + (size_t)o * K_TOT + s * 128 + lane * 4) = *(const uint2*)h;
        }
    } else {
        // X: compact index xi in [0,4096), grid-stride over 8-float groups
        const int xi = (bid / 3) * 2 + m3;
        const size_t n8 = (size_t)M_TOT * K_TOT / 8;
        const size_t tid0 = (size_t)xi * blockDim.x + threadIdx.x;
        const size_t stride = (size_t)4096 * blockDim.x;
        for (size_t g = tid0; g < n8; g += stride) {
            const float4 a = ((const float4*)(x + g * 8))[0];
            const float4 b = ((const float4*)(x + g * 8))[1];
            __half2 o[4];
            o[0] = __floats2half2_rn(a.x, a.y);
            o[1] = __floats2half2_rn(a.z, a.w);
            o[2] = __floats2half2_rn(b.x, b.y);
            o[3] = __floats2half2_rn(b.z, b.w);
            *(uint4*)(g_Xh + g * 8) = *(const uint4*)o;
        }
    }
}

// SW128 swizzle for the cp.async store side (off = row*128 + col_bytes)
__device__ __forceinline__ uint32_t swz(uint32_t off) {
    return off ^ ((off >> 3) & 0x70);
}

// ---------------- GEMM ----------------
__global__ __launch_bounds__(128, 2) void pq_f16_gemm(float* __restrict__ out)
{
    extern __shared__ char smem[];
    const uint32_t sbase = smem_u32(smem);

    const int tid  = threadIdx.x;
    const int wid  = tid >> 5;       // 0..3
    const int lane = tid & 31;
    const int lq   = lane >> 2;
    const int lr   = lane & 3;
    const int sel  = lane >> 3;      // ldmatrix matrix selector 0..3
    const int lrow = lane & 7;

    // grid swizzle: 8x8 tile groups
    const int bid = blockIdx.x;
    const int grp = bid >> 6;
    const int r   = bid & 63;
    const int mt  = (grp & 7) * 8 + (r & 7);
    const int nt  = (grp >> 3) * 8 + (r >> 3);
    const int m0  = mt * BM;
    const int n0  = nt * BN;

    // warp tile 64x64 (2x2 warps)
    const int wm = (wid >> 1) * 64;
    const int wn = (wid & 1) * 64;

    float acc[4][8][4];
#pragma unroll
    for (int mi = 0; mi < 4; mi++)
#pragma unroll
        for (int ni = 0; ni < 8; ni++)
#pragma unroll
            for (int q = 0; q < 4; q++) acc[mi][ni][q] = 0.f;

    // ldmatrix addr = stagebase + rowbase + ((col + ko) ^ sx),  sx=(row&7)*16
    uint32_t a_base[4], a_sx[4], b_base[4], b_sx[4];
    const uint32_t a_col = (uint32_t)((sel >> 1) << 4);
    const uint32_t b_col = (uint32_t)((sel & 1) << 4);
#pragma unroll
    for (int mi = 0; mi < 4; mi++) {
        const int row = wm + mi * 16 + ((sel & 1) << 3) + lrow;
        a_base[mi] = (uint32_t)(row * 128);
        a_sx[mi]   = (uint32_t)((row & 7) * 16);
    }
#pragma unroll
    for (int np = 0; np < 4; np++) {
        const int n = wn + np * 16 + ((sel >> 1) << 3) + lrow;
        b_base[np] = (uint32_t)(n * 128);
        b_sx[np]   = (uint32_t)((n & 7) * 16);
    }

    // cp.async mapping: per operand 1024 x 16B, 128 threads -> 8 each
    const int l_row = tid >> 3;
    const int l_c   = tid & 7;

    const __half* aptr = g_Xh + (size_t)(m0 + l_row) * K_TOT + l_c * 8;
    const __half* bptr = g_Wh + (size_t)(n0 + l_row) * K_TOT + l_c * 8;
    const uint32_t so_base[8] = {
        swz((l_row +   0) * 128 + l_c * 16), swz((l_row +  16) * 128 + l_c * 16),
        swz((l_row +  32) * 128 + l_c * 16), swz((l_row +  48) * 128 + l_c * 16),
        swz((l_row +  64) * 128 + l_c * 16), swz((l_row +  80) * 128 + l_c * 16),
        swz((l_row +  96) * 128 + l_c * 16), swz((l_row + 112) * 128 + l_c * 16)};

    auto load_stage = [&](int st, const __half* ap, const __half* bp) {
        const uint32_t ab = sbase + st * A_STAGE_BYTES;
        const uint32_t bb = sbase + SM_B_OFF + st * B_STAGE_BYTES;
#pragma unroll
        for (int p = 0; p < 8; p++) {
            cpa16(ab + so_base[p], ap + (size_t)(p * 16) * K_TOT);
            cpa16(bb + so_base[p], bp + (size_t)(p * 16) * K_TOT);
        }
    };

    const __half* ald = aptr;
    const __half* bld = bptr;
#pragma unroll
    for (int c = 0; c < STAGES - 1; c++) {
        load_stage(c, ald, bld);
        cp_commit();
        ald += BK; bld += BK;
    }

    // chunk 0 resident; prefetch its k0 fragments into buffer 0
    cp_wait<1>();
    __syncthreads();

    uint32_t af[2][4][4], bf[2][4][4];
#pragma unroll
    for (int mi = 0; mi < 4; mi++)
        ldsm4(af[0][mi], sbase + a_base[mi] + (a_col ^ a_sx[mi]));
#pragma unroll
    for (int np = 0; np < 4; np++)
        ldsm4(bf[0][np], sbase + SM_B_OFF + b_base[np] + (b_col ^ b_sx[np]));

    int st = 0;                 // stage of chunk i
    int st_ld = STAGES - 1;     // stage for the next load
#pragma unroll 1
    for (int i = 0; i < NCHUNK; i++) {
        __syncthreads();             // compute(i-1) done before stage st_ld overwrite

        const uint32_t ab = sbase + st * A_STAGE_BYTES;
        const uint32_t bb = sbase + SM_B_OFF + st * B_STAGE_BYTES;
        const int st_n = (st == STAGES - 1) ? 0 : st + 1;
        const uint32_t ab_n = sbase + st_n * A_STAGE_BYTES;
        const uint32_t bb_n = sbase + SM_B_OFF + st_n * B_STAGE_BYTES;

        if (i + STAGES - 1 < NCHUNK) {
            load_stage(st_ld, ald, bld);
            ald += BK; bld += BK;
        }
        cp_commit();

#pragma unroll
        for (int kg = 0; kg < 4; kg++) {
            const int cur = kg & 1, nxt = cur ^ 1;
            if (kg < 3) {
                // prefetch k-step kg+1 of this chunk
                const uint32_t ko = (uint32_t)((kg + 1) * 32);
#pragma unroll
                for (int mi = 0; mi < 4; mi++)
                    ldsm4(af[nxt][mi], ab + a_base[mi] + ((a_col + ko) ^ a_sx[mi]));
#pragma unroll
                for (int np = 0; np < 4; np++)
                    ldsm4(bf[nxt][np], bb + b_base[np] + ((b_col + ko) ^ b_sx[np]));
            } else if (i + 1 < NCHUNK) {
                // prefetch k0 of chunk i+1 (resident: cp_wait below ran at kg==1)
#pragma unroll
                for (int mi = 0; mi < 4; mi++)
                    ldsm4(af[nxt][mi], ab_n + a_base[mi] + (a_col ^ a_sx[mi]));
#pragma unroll
                for (int np = 0; np < 4; np++)
                    ldsm4(bf[nxt][np], bb_n + b_base[np] + (b_col ^ b_sx[np]));
            }
#pragma unroll
            for (int mi = 0; mi < 4; mi++)
#pragma unroll
                for (int ni = 0; ni < 8; ni++)
                    mma_f16(acc[mi][ni], af[cur][mi], &bf[cur][ni >> 1][(ni & 1) * 2]);
            if (kg == 1) cp_wait<1>();   // chunk i+1 resident (only group i+2 may remain)
        }
        st    = st_n;
        st_ld = (st_ld == STAGES - 1) ? 0 : st_ld + 1;
    }

    // epilogue
#pragma unroll
    for (int mi = 0; mi < 4; mi++) {
#pragma unroll
        for (int ni = 0; ni < 8; ni++) {
            const int row0 = m0 + wm + mi * 16 + lq;
            const int col  = n0 + wn + ni * 8 + 2 * lr;
            *(float2*)&out[(size_t)row0 * N_TOT + col] =
                make_float2(acc[mi][ni][0], acc[mi][ni][1]);
            *(float2*)&out[(size_t)(row0 + 8) * N_TOT + col] =
                make_float2(acc[mi][ni][2], acc[mi][ni][3]);
        }
    }
}

extern "C" void kernel_launch(void* const* d_in, const int* in_sizes, int n_in,
                              void* d_out, int out_size) {
    const float* x         = (const float*)d_in[0];   // [4,2048,4096] fp32
    const float* codebooks = (const float*)d_in[1];   // [32,256,128] fp32
    const int*   assign    = (const int*)d_in[2];     // [4096,32] int32
    float*       out       = (float*)d_out;

    prep_fused_kernel<<<6144, 256>>>(x, codebooks, assign);

    cudaFuncSetAttribute(pq_f16_gemm,
                         cudaFuncAttributeMaxDynamicSharedMemorySize, SMEM_BYTES);
    pq_f16_gemm<<<(M_TOT / BM) * (N_TOT / BN), 128, SMEM_BYTES>>>(out);
}